// round 3
// baseline (speedup 1.0000x reference)
#include <cuda_runtime.h>
#include <cstdint>

#define NODES 100000
#define EMAX  1600000
#define F0 128
#define F1 64
#define F2 32
#define NB_SCAN 196          // ceil(100000/512)
#define NPAD (NB_SCAN*512)   // 100352

// ---- scratch (static device globals: allocation-free) ----
__device__ int   d_degi[NODES];
__device__ int   d_loc[NPAD];
__device__ int   d_part[NB_SCAN];
__device__ int   d_off[NODES + 1];
__device__ int   d_pos[NODES];
__device__ int   d_csr[EMAX];
__device__ float d_dinv[NODES];
__device__ float d_g1[(size_t)NODES * F1];   // x@W1 (UNSCALED)
__device__ float d_h1[(size_t)NODES * F1];   // relu-normalized layer-1 output
__device__ float d_g2[(size_t)NODES * F2];   // (h1@W2)*dinv

// ---- side stream + fork/join events (host objects, created at static init;
//      no device memory allocation involved) ----
struct SideStream {
    cudaStream_t s;
    cudaEvent_t fork, join;
    SideStream() {
        cudaStreamCreateWithFlags(&s, cudaStreamNonBlocking);
        cudaEventCreateWithFlags(&fork, cudaEventDisableTiming);
        cudaEventCreateWithFlags(&join, cudaEventDisableTiming);
    }
};
static SideStream g_ss;

// ================= degree histogram =================
__global__ void k_zero(int n) {
    int i = blockIdx.x * blockDim.x + threadIdx.x;
    if (i < n) d_degi[i] = 0;
}

__global__ void k_count(const int* __restrict__ dst, int e) {
    int i = blockIdx.x * blockDim.x + threadIdx.x;
    if (i < e) atomicAdd(&d_degi[dst[i]], 1);
}

// ================= scan pass 1: per-block exclusive scan + partials ========
__global__ void k_scan1(int n) {
    __shared__ int s[512];
    int i = blockIdx.x * 512 + threadIdx.x;
    int v = (i < n) ? d_degi[i] : 0;
    s[threadIdx.x] = v;
    __syncthreads();
#pragma unroll
    for (int off = 1; off < 512; off <<= 1) {
        int t = (threadIdx.x >= off) ? s[threadIdx.x - off] : 0;
        __syncthreads();
        s[threadIdx.x] += t;
        __syncthreads();
    }
    d_loc[i] = s[threadIdx.x] - v;  // exclusive
    if (threadIdx.x == 511) d_part[blockIdx.x] = s[511];
}

// ================= scan pass 2 (fused): every block re-scans the partials ==
__global__ void k_scan2f(int n, int nb, int e) {
    __shared__ int s[256];
    __shared__ int sOrig[256];
    int t = threadIdx.x;
    if (t < 256) {
        int v = (t < nb) ? d_part[t] : 0;
        s[t] = v;
        sOrig[t] = v;
    }
    __syncthreads();
#pragma unroll
    for (int off = 1; off < 256; off <<= 1) {
        int tv = 0;
        if (t < 256 && t >= off) tv = s[t - off];
        __syncthreads();
        if (t < 256) s[t] += tv;
        __syncthreads();
    }
    int pref = s[blockIdx.x] - sOrig[blockIdx.x];  // exclusive prefix of this block
    int i = blockIdx.x * 512 + t;
    if (i < n) {
        int o = d_loc[i] + pref;
        d_off[i] = o;
        d_pos[i] = o;
        d_dinv[i] = rsqrtf(1.0f + (float)d_degi[i]);  // +1 self-loop
    }
    if (blockIdx.x == 0 && t == 0) d_off[n] = e;
}

// ================= CSR fill =================
__global__ void k_fill(const int* __restrict__ src, const int* __restrict__ dst, int e) {
    int i = blockIdx.x * blockDim.x + threadIdx.x;
    if (i < e) {
        int d = dst[i];
        int p = atomicAdd(&d_pos[d], 1);
        d_csr[p] = src[i];
    }
}

// ================= GEMM1: g1 = x @ W1 (unscaled) =================
// block: 128 nodes x 64 cols, 256 threads, 8x4 register tile, swizzled LDS.128.
__global__ void k_gemm1(const float* __restrict__ x, const float* __restrict__ W, int n) {
    __shared__ float4 xs4[32 * 33];
    __shared__ float  ws[32][68];
    int tid = threadIdx.x;
    int tx = tid & 15, ty = tid >> 4;
    int nodeBase = blockIdx.x * 128;
    float acc[8][4] = {};

    for (int kc = 0; kc < F0; kc += 32) {
#pragma unroll
        for (int i = 0; i < 4; ++i) {
            int flat = i * 256 + tid;
            int row = flat >> 3;
            int c4  = flat & 7;
            int node = nodeBase + row;
            float4 v = make_float4(0.f, 0.f, 0.f, 0.f);
            if (node < n) v = __ldg((const float4*)(x + (size_t)node * F0 + kc + 4 * c4));
            int g = row >> 2, el = row & 3;
            const float vv[4] = {v.x, v.y, v.z, v.w};
#pragma unroll
            for (int j = 0; j < 4; ++j) {
                int k = 4 * c4 + j;
                float* p = (float*)&xs4[k * 33 + (g ^ ((k >> 2) & 7))];
                p[el] = vv[j];
            }
        }
#pragma unroll
        for (int i = 0; i < 2; ++i) {
            int flat = i * 256 + tid;
            int k = flat >> 4;
            int c4 = flat & 15;
            float4 w = __ldg((const float4*)(W + (size_t)(kc + k) * F1 + 4 * c4));
            *(float4*)&ws[k][4 * c4] = w;
        }
        __syncthreads();
#pragma unroll
        for (int k = 0; k < 32; ++k) {
            int swz = (k >> 2) & 7;
            float4 A0 = xs4[k * 33 + ((2 * ty) ^ swz)];
            float4 A1 = xs4[k * 33 + ((2 * ty + 1) ^ swz)];
            float4 B  = *(const float4*)&ws[k][4 * tx];
            float a[8] = {A0.x, A0.y, A0.z, A0.w, A1.x, A1.y, A1.z, A1.w};
            float b[4] = {B.x, B.y, B.z, B.w};
#pragma unroll
            for (int m = 0; m < 8; ++m)
#pragma unroll
                for (int q = 0; q < 4; ++q)
                    acc[m][q] += a[m] * b[q];
        }
        __syncthreads();
    }

#pragma unroll
    for (int m = 0; m < 8; ++m) {
        int node = nodeBase + 8 * ty + m;
        if (node < n) {
            float4 o = make_float4(acc[m][0], acc[m][1], acc[m][2], acc[m][3]);
            *(float4*)(d_g1 + (size_t)node * F1 + 4 * tx) = o;
        }
    }
}

// ================= Gather layer1 ==================================
// h1 = relu(dinv[d]*(sum_s dinv[s]*g1[s] + dinv[d]*g1[d]) + b1)
// 16 lanes per node, float4 per lane (64 feats), edge loop unrolled x4.
__global__ void k_gather1(const float* __restrict__ b1, int n) {
    int grp = threadIdx.x >> 4, lane = threadIdx.x & 15;
    int node = blockIdx.x * 16 + grp;
    if (node >= n) return;
    const float4* g1 = (const float4*)d_g1;
    float dv = d_dinv[node];
    float4 sv = __ldg(&g1[(size_t)node * 16 + lane]);  // self loop
    float4 acc;
    acc.x = sv.x * dv; acc.y = sv.y * dv; acc.z = sv.z * dv; acc.w = sv.w * dv;
    int beg = d_off[node], end = d_off[node + 1];
    int j = beg;
    for (; j + 4 <= end; j += 4) {
        int s0 = __ldg(&d_csr[j + 0]);
        int s1 = __ldg(&d_csr[j + 1]);
        int s2 = __ldg(&d_csr[j + 2]);
        int s3 = __ldg(&d_csr[j + 3]);
        float w0 = __ldg(&d_dinv[s0]);
        float w1 = __ldg(&d_dinv[s1]);
        float w2 = __ldg(&d_dinv[s2]);
        float w3 = __ldg(&d_dinv[s3]);
        float4 v0 = __ldg(&g1[(size_t)s0 * 16 + lane]);
        float4 v1 = __ldg(&g1[(size_t)s1 * 16 + lane]);
        float4 v2 = __ldg(&g1[(size_t)s2 * 16 + lane]);
        float4 v3 = __ldg(&g1[(size_t)s3 * 16 + lane]);
        acc.x += v0.x * w0 + v1.x * w1 + v2.x * w2 + v3.x * w3;
        acc.y += v0.y * w0 + v1.y * w1 + v2.y * w2 + v3.y * w3;
        acc.z += v0.z * w0 + v1.z * w1 + v2.z * w2 + v3.z * w3;
        acc.w += v0.w * w0 + v1.w * w1 + v2.w * w2 + v3.w * w3;
    }
    for (; j < end; ++j) {
        int s = __ldg(&d_csr[j]);
        float w = __ldg(&d_dinv[s]);
        float4 v = __ldg(&g1[(size_t)s * 16 + lane]);
        acc.x += v.x * w; acc.y += v.y * w; acc.z += v.z * w; acc.w += v.w * w;
    }
    float4 bb = __ldg(&((const float4*)b1)[lane]);
    float4 h;
    h.x = fmaxf(fmaf(acc.x, dv, bb.x), 0.f);
    h.y = fmaxf(fmaf(acc.y, dv, bb.y), 0.f);
    h.z = fmaxf(fmaf(acc.z, dv, bb.z), 0.f);
    h.w = fmaxf(fmaf(acc.w, dv, bb.w), 0.f);
    ((float4*)d_h1)[(size_t)node * 16 + lane] = h;
}

// ================= GEMM2: g2 = (h1 @ W2) * dinv =================
__global__ void k_gemm2(const float* __restrict__ W2, int n) {
    __shared__ float4 xs4[64 * 33];
    __shared__ float  ws[64][36];
    int tid = threadIdx.x;
    int tx = tid & 15, ty = tid >> 4;
    int nodeBase = blockIdx.x * 128;
    float acc[8][2] = {};

#pragma unroll
    for (int i = 0; i < 8; ++i) {
        int flat = i * 256 + tid;
        int row = flat >> 4;
        int c4  = flat & 15;
        int node = nodeBase + row;
        float4 v = make_float4(0.f, 0.f, 0.f, 0.f);
        if (node < n) v = __ldg((const float4*)(d_h1 + (size_t)node * F1 + 4 * c4));
        int g = row >> 2, el = row & 3;
        const float vv[4] = {v.x, v.y, v.z, v.w};
#pragma unroll
        for (int j = 0; j < 4; ++j) {
            int k = 4 * c4 + j;
            float* p = (float*)&xs4[k * 33 + (g ^ ((k >> 2) & 7))];
            p[el] = vv[j];
        }
    }
#pragma unroll
    for (int i = 0; i < 2; ++i) {
        int flat = i * 256 + tid;
        int k = flat >> 3;
        int c4 = flat & 7;
        float4 w = __ldg((const float4*)(W2 + (size_t)k * F2 + 4 * c4));
        *(float4*)&ws[k][4 * c4] = w;
    }
    __syncthreads();

#pragma unroll
    for (int k = 0; k < 64; ++k) {
        int swz = (k >> 2) & 7;
        float4 A0 = xs4[k * 33 + ((2 * ty) ^ swz)];
        float4 A1 = xs4[k * 33 + ((2 * ty + 1) ^ swz)];
        float b0 = ws[k][2 * tx + 0];
        float b1 = ws[k][2 * tx + 1];
        float a[8] = {A0.x, A0.y, A0.z, A0.w, A1.x, A1.y, A1.z, A1.w};
#pragma unroll
        for (int m = 0; m < 8; ++m) {
            acc[m][0] += a[m] * b0;
            acc[m][1] += a[m] * b1;
        }
    }

#pragma unroll
    for (int m = 0; m < 8; ++m) {
        int node = nodeBase + 8 * ty + m;
        if (node < n) {
            float dv = d_dinv[node];
            float2 o = make_float2(acc[m][0] * dv, acc[m][1] * dv);
            *(float2*)(d_g2 + (size_t)node * F2 + 2 * tx) = o;
        }
    }
}

// ================= Gather layer2: out = (sum g2[s] + g2[d])*dinv + b2 ====
// 8 lanes per node, float4 per lane (32 feats), unrolled x4.
__global__ void k_gather2(const float* __restrict__ b2, float* __restrict__ out, int n) {
    int grp = threadIdx.x >> 3, lane = threadIdx.x & 7;
    int node = blockIdx.x * 32 + grp;
    if (node >= n) return;
    const float4* g2 = (const float4*)d_g2;
    float4 acc = __ldg(&g2[(size_t)node * 8 + lane]);  // self loop (pre-scaled)
    int beg = d_off[node], end = d_off[node + 1];
    int j = beg;
    for (; j + 4 <= end; j += 4) {
        int s0 = __ldg(&d_csr[j + 0]);
        int s1 = __ldg(&d_csr[j + 1]);
        int s2 = __ldg(&d_csr[j + 2]);
        int s3 = __ldg(&d_csr[j + 3]);
        float4 v0 = __ldg(&g2[(size_t)s0 * 8 + lane]);
        float4 v1 = __ldg(&g2[(size_t)s1 * 8 + lane]);
        float4 v2 = __ldg(&g2[(size_t)s2 * 8 + lane]);
        float4 v3 = __ldg(&g2[(size_t)s3 * 8 + lane]);
        acc.x += (v0.x + v1.x) + (v2.x + v3.x);
        acc.y += (v0.y + v1.y) + (v2.y + v3.y);
        acc.z += (v0.z + v1.z) + (v2.z + v3.z);
        acc.w += (v0.w + v1.w) + (v2.w + v3.w);
    }
    for (; j < end; ++j) {
        int s = __ldg(&d_csr[j]);
        float4 v = __ldg(&g2[(size_t)s * 8 + lane]);
        acc.x += v.x; acc.y += v.y; acc.z += v.z; acc.w += v.w;
    }
    float dv = d_dinv[node];
    float4 bb = __ldg(&((const float4*)b2)[lane]);
    float4 o;
    o.x = fmaf(acc.x, dv, bb.x);
    o.y = fmaf(acc.y, dv, bb.y);
    o.z = fmaf(acc.z, dv, bb.z);
    o.w = fmaf(acc.w, dv, bb.w);
    ((float4*)out)[(size_t)node * 8 + lane] = o;
}

extern "C" void kernel_launch(void* const* d_in, const int* in_sizes, int n_in,
                              void* d_out, int out_size) {
    const float* x  = (const float*)d_in[0];
    const int*   ei = (const int*)d_in[1];
    const float* W1 = (const float*)d_in[2];
    const float* b1 = (const float*)d_in[3];
    const float* W2 = (const float*)d_in[4];
    const float* b2 = (const float*)d_in[5];
    float* out = (float*)d_out;

    int n = in_sizes[0] / F0;   // 100000
    int e = in_sizes[1] / 2;    // 1600000
    const int* src = ei;
    const int* dst = ei + e;
    int nb = (n + 511) / 512;   // 196

    // Fork: GEMM1 (independent of graph structure) on side stream.
    cudaEventRecord(g_ss.fork, 0);
    cudaStreamWaitEvent(g_ss.s, g_ss.fork, 0);
    k_gemm1<<<(n + 127) / 128, 256, 0, g_ss.s>>>(x, W1, n);

    // CSR build on main stream (overlapped with GEMM1).
    k_zero<<<(n + 255) / 256, 256>>>(n);
    k_count<<<(e + 255) / 256, 256>>>(dst, e);
    k_scan1<<<nb, 512>>>(n);
    k_scan2f<<<nb, 512>>>(n, nb, e);
    k_fill<<<(e + 255) / 256, 256>>>(src, dst, e);

    // Join: gather needs both CSR and g1.
    cudaEventRecord(g_ss.join, g_ss.s);
    cudaStreamWaitEvent(0, g_ss.join, 0);

    k_gather1<<<(n + 15) / 16, 256>>>(b1, n);
    k_gemm2<<<(n + 127) / 128, 256>>>(W2, n);
    k_gather2<<<(n + 31) / 32, 256>>>(b2, out, n);
}